// round 1
// baseline (speedup 1.0000x reference)
#include <cuda_runtime.h>
#include <math.h>

#define B_  2
#define L_  2048
#define D_  2048
#define H_  16
#define HD_ 128

// Scratch (static __device__ — no runtime allocation)
__device__ float g_q[(size_t)B_ * H_ * L_ * HD_];
__device__ float g_k[(size_t)B_ * H_ * L_ * HD_];
__device__ float g_v[(size_t)B_ * H_ * L_ * HD_];
__device__ float g_c[(size_t)B_ * L_ * H_ * HD_];

// ---------------------------------------------------------------------------
// SGEMM: C = A(MxK) @ B(KxN), row-major, 128x128 block tile, BK=16,
// 256 threads, 8x8 per-thread microtile.
// MODE 0: scatter epilogue to (B,H,L,hd) layout.  MODE 1: plain row-major.
// ---------------------------------------------------------------------------
template <int MODE>
__global__ __launch_bounds__(256) void sgemm128(
    const float* __restrict__ A, const float* __restrict__ Bm,
    float* __restrict__ C, int M, int N, int K)
{
    __shared__ float Ast[16][132];   // A tile transposed: Ast[k][m]
    __shared__ float Bs[16][132];    // B tile: Bs[k][n]

    const int tid = threadIdx.x;
    const int tx = tid & 15, ty = tid >> 4;
    const int bx = blockIdx.x, by = blockIdx.y;

    const float* Ablk = A + (size_t)(by * 128) * K;
    const float* Bblk = Bm + (size_t)(bx * 128);

    float acc[8][8];
#pragma unroll
    for (int i = 0; i < 8; i++)
#pragma unroll
        for (int j = 0; j < 8; j++) acc[i][j] = 0.f;

    for (int k0 = 0; k0 < K; k0 += 16) {
#pragma unroll
        for (int it = 0; it < 2; it++) {
            int item = tid + it * 256;              // 0..511
            int ar = item >> 2, ac = (item & 3) << 2;
            float4 va = *(const float4*)(Ablk + (size_t)ar * K + k0 + ac);
            Ast[ac + 0][ar] = va.x; Ast[ac + 1][ar] = va.y;
            Ast[ac + 2][ar] = va.z; Ast[ac + 3][ar] = va.w;
            int br = item >> 5, bc = (item & 31) << 2;
            float4 vb = *(const float4*)(Bblk + (size_t)(k0 + br) * N + bc);
            Bs[br][bc + 0] = vb.x; Bs[br][bc + 1] = vb.y;
            Bs[br][bc + 2] = vb.z; Bs[br][bc + 3] = vb.w;
        }
        __syncthreads();

#pragma unroll
        for (int kk = 0; kk < 16; kk++) {
            float a[8], b[8];
#pragma unroll
            for (int u = 0; u < 8; u++) a[u] = Ast[kk][ty * 8 + u];
#pragma unroll
            for (int u = 0; u < 8; u++) b[u] = Bs[kk][tx * 8 + u];
#pragma unroll
            for (int i = 0; i < 8; i++)
#pragma unroll
                for (int j = 0; j < 8; j++)
                    acc[i][j] = fmaf(a[i], b[j], acc[i][j]);
        }
        __syncthreads();
    }

#pragma unroll
    for (int i = 0; i < 8; i++) {
        int m = by * 128 + ty * 8 + i;
#pragma unroll
        for (int j4 = 0; j4 < 2; j4++) {
            int n = bx * 128 + tx * 8 + j4 * 4;
            float4 r = make_float4(acc[i][j4 * 4 + 0], acc[i][j4 * 4 + 1],
                                   acc[i][j4 * 4 + 2], acc[i][j4 * 4 + 3]);
            if (MODE == 0) {
                int b = m >> 11, l = m & (L_ - 1);
                int h = n >> 7, d = n & (HD_ - 1);
                *(float4*)(C + ((((size_t)b * H_ + h) * L_ + l) * HD_ + d)) = r;
            } else {
                *(float4*)(C + (size_t)m * N + n) = r;
            }
        }
    }
}

// ---------------------------------------------------------------------------
// RoPE in-place on q and k, layout (B,H,L,hd). One thread per (b,h,l,pair).
// ---------------------------------------------------------------------------
__global__ void rope_kernel(float* __restrict__ qb, float* __restrict__ kb)
{
    int idx = blockIdx.x * blockDim.x + threadIdx.x;
    if (idx >= B_ * H_ * L_ * 64) return;
    int j  = idx & 63;
    int l  = (idx >> 6) & (L_ - 1);
    int bh = idx >> 17;

    float freq = expf(-9.210340371976184f * (float)j * (1.0f / 64.0f)); // 10000^(-j/64)
    float ang = (float)l * freq;
    float s, c;
    sincosf(ang, &s, &c);

    size_t base = ((size_t)bh * L_ + l) * HD_ + j;
    float q1 = qb[base], q2 = qb[base + 64];
    qb[base]      = q1 * c - q2 * s;
    qb[base + 64] = q1 * s + q2 * c;
    float k1 = kb[base], k2 = kb[base + 64];
    kb[base]      = k1 * c - k2 * s;
    kb[base + 64] = k1 * s + k2 * c;
}

// ---------------------------------------------------------------------------
// Attention + memory path. One block = one (b,h) x 64 query rows.
// Flash-style online softmax over 32 key tiles of 64.
// Q/K stored in smem as float4 cells [d4][row] (d4-major, row-padded 65)
// so the score GEMM reads are conflict-free vectorized.
// Epilogue: q_f = elu(q)+1, mem_out = q_f @ memory, denom = q_f . norm_term,
// combined = g*mem_out/denom + (1-g)*attn_out -> g_c in (B, L, H*hd).
// ---------------------------------------------------------------------------
__global__ __launch_bounds__(256) void attn_kernel(
    const float* __restrict__ qb, const float* __restrict__ kb,
    const float* __restrict__ vb, const float* __restrict__ gatep,
    const float* __restrict__ memp, const float* __restrict__ normp,
    float* __restrict__ cb)
{
    extern __shared__ char smemraw[];
    float4* Qst4 = (float4*)smemraw;          // 32*65 cells  (33280 B)
    float4* Kst4 = Qst4 + 32 * 65;            // 32*65 cells  (33280 B)
    float*  Vs   = (float*)(Kst4 + 32 * 65);  // 64*128 floats (32768 B)
    float*  Ps   = Vs + 64 * 128;             // 64*64 floats  (16384 B)
    float*  Ms   = (float*)Kst4;              // 128*128 floats, aliases Kst4+Vs
    float*  Ns   = Ps;                        // 128 floats, aliases Ps

    const int tid = threadIdx.x;
    const int tx = tid & 15, ty = tid >> 4;
    const int qt = blockIdx.x;                // 0..31
    const int bh = blockIdx.y;                // 0..31
    const int h  = bh & (H_ - 1);
    const int b  = bh >> 4;

    const float* qblk  = qb + ((size_t)bh * L_ + qt * 64) * HD_;
    const float* kbase = kb + (size_t)bh * L_ * HD_;
    const float* vbase = vb + (size_t)bh * L_ * HD_;

    // Load Q tile transposed into float4 cells
#pragma unroll
    for (int it = 0; it < 8; it++) {
        int item = tid + it * 256;            // 0..2047
        int r = item >> 5, d4 = item & 31;
        Qst4[d4 * 65 + r] = *(const float4*)(qblk + r * HD_ + d4 * 4);
    }

    float o[4][8];
#pragma unroll
    for (int i = 0; i < 4; i++)
#pragma unroll
        for (int j = 0; j < 8; j++) o[i][j] = 0.f;
    float mrow[4] = {-1e30f, -1e30f, -1e30f, -1e30f};
    float lrow[4] = {0.f, 0.f, 0.f, 0.f};

    __syncthreads();

    const float scale = 0.08838834764831845f;  // 128^-0.5

    for (int kt = 0; kt < 32; kt++) {
        const float* kblk = kbase + (size_t)kt * 64 * HD_;
        const float* vblk = vbase + (size_t)kt * 64 * HD_;
#pragma unroll
        for (int it = 0; it < 8; it++) {
            int item = tid + it * 256;
            int r = item >> 5, d4 = item & 31;
            Kst4[d4 * 65 + r] = *(const float4*)(kblk + r * HD_ + d4 * 4);
            *(float4*)(Vs + r * HD_ + d4 * 4) = *(const float4*)(vblk + r * HD_ + d4 * 4);
        }
        __syncthreads();

        // S = Q K^T (4x4 per thread, rows ty*4+i, cols tx*4+j)
        float s[4][4];
#pragma unroll
        for (int i = 0; i < 4; i++)
#pragma unroll
            for (int j = 0; j < 4; j++) s[i][j] = 0.f;

#pragma unroll 2
        for (int d4 = 0; d4 < 32; d4++) {
            float4 qv[4], kv[4];
#pragma unroll
            for (int i = 0; i < 4; i++) qv[i] = Qst4[d4 * 65 + ty * 4 + i];
#pragma unroll
            for (int j = 0; j < 4; j++) kv[j] = Kst4[d4 * 65 + tx * 4 + j];
#pragma unroll
            for (int i = 0; i < 4; i++)
#pragma unroll
                for (int j = 0; j < 4; j++) {
                    s[i][j] = fmaf(qv[i].x, kv[j].x, s[i][j]);
                    s[i][j] = fmaf(qv[i].y, kv[j].y, s[i][j]);
                    s[i][j] = fmaf(qv[i].z, kv[j].z, s[i][j]);
                    s[i][j] = fmaf(qv[i].w, kv[j].w, s[i][j]);
                }
        }

        // Online softmax (row reduce across the 16 threads of each row)
#pragma unroll
        for (int i = 0; i < 4; i++) {
            float tmax = fmaxf(fmaxf(s[i][0], s[i][1]), fmaxf(s[i][2], s[i][3])) * scale;
#pragma unroll
            for (int off = 8; off >= 1; off >>= 1)
                tmax = fmaxf(tmax, __shfl_xor_sync(0xffffffffu, tmax, off));
            float newm = fmaxf(mrow[i], tmax);
            float corr = expf(mrow[i] - newm);
            mrow[i] = newm;
            float psum = 0.f;
#pragma unroll
            for (int j = 0; j < 4; j++) {
                float p = expf(s[i][j] * scale - newm);
                s[i][j] = p;
                psum += p;
            }
#pragma unroll
            for (int off = 8; off >= 1; off >>= 1)
                psum += __shfl_xor_sync(0xffffffffu, psum, off);
            lrow[i] = lrow[i] * corr + psum;
#pragma unroll
            for (int jj = 0; jj < 8; jj++) o[i][jj] *= corr;
            *(float4*)&Ps[(ty * 4 + i) * 64 + tx * 4] =
                make_float4(s[i][0], s[i][1], s[i][2], s[i][3]);
        }
        __syncthreads();

        // O += P @ V  (4 rows x 8 cols per thread, cols tx*8+j)
#pragma unroll 2
        for (int c = 0; c < 64; c++) {
            float4 v0 = *(const float4*)(Vs + c * HD_ + tx * 8);
            float4 v1 = *(const float4*)(Vs + c * HD_ + tx * 8 + 4);
#pragma unroll
            for (int i = 0; i < 4; i++) {
                float p = Ps[(ty * 4 + i) * 64 + c];
                o[i][0] = fmaf(p, v0.x, o[i][0]);
                o[i][1] = fmaf(p, v0.y, o[i][1]);
                o[i][2] = fmaf(p, v0.z, o[i][2]);
                o[i][3] = fmaf(p, v0.w, o[i][3]);
                o[i][4] = fmaf(p, v1.x, o[i][4]);
                o[i][5] = fmaf(p, v1.y, o[i][5]);
                o[i][6] = fmaf(p, v1.z, o[i][6]);
                o[i][7] = fmaf(p, v1.w, o[i][7]);
            }
        }
        __syncthreads();
    }

    // ---- memory path: mem_out = (elu(q)+1) @ memory, denom = (elu(q)+1).norm ----
    const float* mptr = memp + (size_t)bh * HD_ * HD_;
#pragma unroll
    for (int it = 0; it < 16; it++) {
        int item = tid + it * 256;            // 0..4095
        *(float4*)(Ms + item * 4) = *(const float4*)(mptr + item * 4);
    }
    if (tid < 32)
        *(float4*)(Ns + tid * 4) = *(const float4*)(normp + (size_t)bh * HD_ + tid * 4);
    __syncthreads();

    float acc2[4][8];
#pragma unroll
    for (int i = 0; i < 4; i++)
#pragma unroll
        for (int j = 0; j < 8; j++) acc2[i][j] = 0.f;
    float den[4] = {0.f, 0.f, 0.f, 0.f};

    const float* Qsf = (const float*)Qst4;
    for (int d4 = 0; d4 < 32; d4++) {
        float qf[4][4];
#pragma unroll
        for (int i = 0; i < 4; i++) {
            const float* qc = Qsf + (size_t)(d4 * 65 + ty * 4 + i) * 4;
#pragma unroll
            for (int u = 0; u < 4; u++) {
                float qv = qc[u];
                qf[i][u] = qv > 0.f ? qv + 1.f : expf(qv);
            }
        }
#pragma unroll
        for (int u = 0; u < 4; u++) {
            int d = d4 * 4 + u;
            float nr = Ns[d];
            float4 m0 = *(const float4*)(Ms + d * HD_ + tx * 8);
            float4 m1 = *(const float4*)(Ms + d * HD_ + tx * 8 + 4);
#pragma unroll
            for (int i = 0; i < 4; i++) {
                float q = qf[i][u];
                den[i]     = fmaf(q, nr,   den[i]);
                acc2[i][0] = fmaf(q, m0.x, acc2[i][0]);
                acc2[i][1] = fmaf(q, m0.y, acc2[i][1]);
                acc2[i][2] = fmaf(q, m0.z, acc2[i][2]);
                acc2[i][3] = fmaf(q, m0.w, acc2[i][3]);
                acc2[i][4] = fmaf(q, m1.x, acc2[i][4]);
                acc2[i][5] = fmaf(q, m1.y, acc2[i][5]);
                acc2[i][6] = fmaf(q, m1.z, acc2[i][6]);
                acc2[i][7] = fmaf(q, m1.w, acc2[i][7]);
            }
        }
    }

    float g  = 1.f / (1.f + expf(-gatep[h]));
    float og = 1.f - g;
#pragma unroll
    for (int i = 0; i < 4; i++) {
        float invl = og / lrow[i];
        float invd = g / den[i];
        int l = qt * 64 + ty * 4 + i;
        float* dst = cb + ((size_t)b * L_ + l) * (H_ * HD_) + h * HD_ + tx * 8;
        float4 r0, r1;
        r0.x = acc2[i][0] * invd + o[i][0] * invl;
        r0.y = acc2[i][1] * invd + o[i][1] * invl;
        r0.z = acc2[i][2] * invd + o[i][2] * invl;
        r0.w = acc2[i][3] * invd + o[i][3] * invl;
        r1.x = acc2[i][4] * invd + o[i][4] * invl;
        r1.y = acc2[i][5] * invd + o[i][5] * invl;
        r1.z = acc2[i][6] * invd + o[i][6] * invl;
        r1.w = acc2[i][7] * invd + o[i][7] * invl;
        *(float4*)dst       = r0;
        *(float4*)(dst + 4) = r1;
    }
}

// ---------------------------------------------------------------------------

extern "C" void kernel_launch(void* const* d_in, const int* in_sizes, int n_in,
                              void* d_out, int out_size)
{
    const float* x      = (const float*)d_in[0];
    const float* Wq     = (const float*)d_in[1];
    const float* Wk     = (const float*)d_in[2];
    const float* Wv     = (const float*)d_in[3];
    const float* Wo     = (const float*)d_in[4];
    const float* gate   = (const float*)d_in[5];
    const float* memory = (const float*)d_in[6];
    const float* norm   = (const float*)d_in[7];
    float* out = (float*)d_out;

    float *qb, *kb, *vb, *cb;
    cudaGetSymbolAddress((void**)&qb, g_q);
    cudaGetSymbolAddress((void**)&kb, g_k);
    cudaGetSymbolAddress((void**)&vb, g_v);
    cudaGetSymbolAddress((void**)&cb, g_c);

    dim3 gg(16, 32);   // N/128, M/128
    sgemm128<0><<<gg, 256>>>(x, Wq, qb, B_ * L_, H_ * HD_, D_);
    sgemm128<0><<<gg, 256>>>(x, Wk, kb, B_ * L_, H_ * HD_, D_);
    sgemm128<0><<<gg, 256>>>(x, Wv, vb, B_ * L_, H_ * HD_, D_);

    int nrope = B_ * H_ * L_ * 64;
    rope_kernel<<<nrope / 256, 256>>>(qb, kb);

    int smem = (32 * 65 * 2) * 16 + 64 * 128 * 4 + 64 * 64 * 4;  // 115712 B
    cudaFuncSetAttribute(attn_kernel, cudaFuncAttributeMaxDynamicSharedMemorySize, smem);
    attn_kernel<<<dim3(32, 32), 256, smem>>>(qb, kb, vb, gate, memory, norm, cb);

    sgemm128<1><<<gg, 256>>>(cb, Wo, out, B_ * L_, H_ * HD_, D_);
}

// round 3
// speedup vs baseline: 1.4377x; 1.4377x over previous
#include <cuda_runtime.h>
#include <math.h>

#define B_  2
#define L_  2048
#define D_  2048
#define H_  16
#define HD_ 128

// Scratch (static __device__ — no runtime allocation)
__device__ float g_q[(size_t)B_ * H_ * L_ * HD_];
__device__ float g_k[(size_t)B_ * H_ * L_ * HD_];
__device__ float g_v[(size_t)B_ * H_ * L_ * HD_];
__device__ float g_c[(size_t)B_ * L_ * H_ * HD_];

__device__ __forceinline__ unsigned f2tf32(float f) {
    unsigned u;
    asm("cvt.rna.tf32.f32 %0, %1;" : "=r"(u) : "f"(f));
    return u;
}

// ---------------------------------------------------------------------------
// TF32 tensor-core GEMM: C = A(MxK) @ B(KxN), row-major.
// 128x128 block, BK=32, 256 threads = 8 warps of 64x32 warp tiles,
// mma.sync.m16n8k8 tf32, fp32 accumulate. Double-buffered smem.
// MODE 0: scatter epilogue to (B,H,L,hd). MODE 1: plain row-major.
// ---------------------------------------------------------------------------
#define AS_LD 36   // A smem row pitch (floats): conflict-free a-frag LDS
#define BS_LD 132  // B smem row pitch (floats): conflict-free b-frag LDS

template <int MODE>
__global__ __launch_bounds__(256, 1) void gemm_tf32(
    const float* __restrict__ A, const float* __restrict__ Bm,
    float* __restrict__ C, int M, int N, int K)
{
    extern __shared__ unsigned sm[];
    unsigned* As = sm;                       // [2][128][AS_LD]
    unsigned* Bs = sm + 2 * 128 * AS_LD;     // [2][32][BS_LD]

    const int tid  = threadIdx.x;
    const int warp = tid >> 5, lane = tid & 31;
    const int qr = lane >> 2, qc = lane & 3;
    const int wm = (warp & 1) * 64;          // warp m offset in block
    const int wn = (warp >> 1) * 32;         // warp n offset in block
    const int bm = blockIdx.y * 128, bn = blockIdx.x * 128;

    // global load coords
    const int ar = tid >> 3, ac4 = tid & 7;       // A: rows ar+it*32, it=0..3
    const int br = tid >> 5, bc4 = tid & 31;      // B: rows br+it*8,  it=0..3

    float acc[4][4][4];
#pragma unroll
    for (int mt = 0; mt < 4; mt++)
#pragma unroll
        for (int nt = 0; nt < 4; nt++)
#pragma unroll
            for (int u = 0; u < 4; u++) acc[mt][nt][u] = 0.f;

    float4 ra[4], rb[4];

    // prologue: load chunk 0
#pragma unroll
    for (int it = 0; it < 4; it++)
        ra[it] = *(const float4*)(A + (size_t)(bm + ar + it * 32) * K + ac4 * 4);
#pragma unroll
    for (int it = 0; it < 4; it++)
        rb[it] = *(const float4*)(Bm + (size_t)(br + it * 8) * N + bn + bc4 * 4);

    int p = 0;
#pragma unroll
    for (int it = 0; it < 4; it++) {
        unsigned* d = As + (ar + it * 32) * AS_LD + ac4 * 4;
        d[0] = f2tf32(ra[it].x); d[1] = f2tf32(ra[it].y);
        d[2] = f2tf32(ra[it].z); d[3] = f2tf32(ra[it].w);
    }
#pragma unroll
    for (int it = 0; it < 4; it++) {
        unsigned* d = Bs + (br + it * 8) * BS_LD + bc4 * 4;
        d[0] = f2tf32(rb[it].x); d[1] = f2tf32(rb[it].y);
        d[2] = f2tf32(rb[it].z); d[3] = f2tf32(rb[it].w);
    }
    __syncthreads();

    const int NCHUNK = K >> 5;   // K/32
    for (int ch = 0; ch < NCHUNK; ch++) {
        // prefetch next chunk into registers
        if (ch + 1 < NCHUNK) {
            int k0 = (ch + 1) << 5;
#pragma unroll
            for (int it = 0; it < 4; it++)
                ra[it] = *(const float4*)(A + (size_t)(bm + ar + it * 32) * K + k0 + ac4 * 4);
#pragma unroll
            for (int it = 0; it < 4; it++)
                rb[it] = *(const float4*)(Bm + (size_t)(k0 + br + it * 8) * N + bn + bc4 * 4);
        }

        const unsigned* Ab = As + p * 128 * AS_LD;
        const unsigned* Bb = Bs + p * 32 * BS_LD;

#pragma unroll
        for (int s = 0; s < 4; s++) {
            const int kb = s * 8;
            unsigned a[4][4], b[4][2];
#pragma unroll
            for (int mt = 0; mt < 4; mt++) {
                int m = wm + mt * 16 + qr;
                a[mt][0] = Ab[m * AS_LD + kb + qc];
                a[mt][1] = Ab[(m + 8) * AS_LD + kb + qc];
                a[mt][2] = Ab[m * AS_LD + kb + qc + 4];
                a[mt][3] = Ab[(m + 8) * AS_LD + kb + qc + 4];
            }
#pragma unroll
            for (int nt = 0; nt < 4; nt++) {
                int n = wn + nt * 8 + qr;
                b[nt][0] = Bb[(kb + qc) * BS_LD + n];
                b[nt][1] = Bb[(kb + qc + 4) * BS_LD + n];
            }
#pragma unroll
            for (int mt = 0; mt < 4; mt++)
#pragma unroll
                for (int nt = 0; nt < 4; nt++) {
                    asm volatile(
                        "mma.sync.aligned.m16n8k8.row.col.f32.tf32.tf32.f32 "
                        "{%0,%1,%2,%3},{%4,%5,%6,%7},{%8,%9},{%0,%1,%2,%3};\n"
                        : "+f"(acc[mt][nt][0]), "+f"(acc[mt][nt][1]),
                          "+f"(acc[mt][nt][2]), "+f"(acc[mt][nt][3])
                        : "r"(a[mt][0]), "r"(a[mt][1]), "r"(a[mt][2]), "r"(a[mt][3]),
                          "r"(b[nt][0]), "r"(b[nt][1]));
                }
        }

        if (ch + 1 < NCHUNK) {
            int q = p ^ 1;
            unsigned* Aw = As + q * 128 * AS_LD;
            unsigned* Bw = Bs + q * 32 * BS_LD;
#pragma unroll
            for (int it = 0; it < 4; it++) {
                unsigned* d = Aw + (ar + it * 32) * AS_LD + ac4 * 4;
                d[0] = f2tf32(ra[it].x); d[1] = f2tf32(ra[it].y);
                d[2] = f2tf32(ra[it].z); d[3] = f2tf32(ra[it].w);
            }
#pragma unroll
            for (int it = 0; it < 4; it++) {
                unsigned* d = Bw + (br + it * 8) * BS_LD + bc4 * 4;
                d[0] = f2tf32(rb[it].x); d[1] = f2tf32(rb[it].y);
                d[2] = f2tf32(rb[it].z); d[3] = f2tf32(rb[it].w);
            }
            __syncthreads();
            p = q;
        }
    }

    // epilogue: c0,c1 at (row, 2qc), c2,c3 at (row+8, 2qc)
#pragma unroll
    for (int mt = 0; mt < 4; mt++) {
#pragma unroll
        for (int nt = 0; nt < 4; nt++) {
            int row = bm + wm + mt * 16 + qr;
            int col = bn + wn + nt * 8 + 2 * qc;
            float2 r0 = make_float2(acc[mt][nt][0], acc[mt][nt][1]);
            float2 r1 = make_float2(acc[mt][nt][2], acc[mt][nt][3]);
            if (MODE == 0) {
                int b0 = row >> 11, l0 = row & (L_ - 1);
                int h = col >> 7, d = col & (HD_ - 1);
                *(float2*)(C + ((((size_t)b0 * H_ + h) * L_ + l0) * HD_ + d)) = r0;
                int row1 = row + 8;
                int b1 = row1 >> 11, l1 = row1 & (L_ - 1);
                *(float2*)(C + ((((size_t)b1 * H_ + h) * L_ + l1) * HD_ + d)) = r1;
            } else {
                *(float2*)(C + (size_t)row * N + col) = r0;
                *(float2*)(C + (size_t)(row + 8) * N + col) = r1;
            }
        }
    }
}

// ---------------------------------------------------------------------------
// RoPE in-place on q and k, layout (B,H,L,hd).
// ---------------------------------------------------------------------------
__global__ void rope_kernel(float* __restrict__ qb, float* __restrict__ kb)
{
    int idx = blockIdx.x * blockDim.x + threadIdx.x;
    if (idx >= B_ * H_ * L_ * 64) return;
    int j  = idx & 63;
    int l  = (idx >> 6) & (L_ - 1);
    int bh = idx >> 17;

    float freq = expf(-9.210340371976184f * (float)j * (1.0f / 64.0f));
    float ang = (float)l * freq;
    float s, c;
    sincosf(ang, &s, &c);

    size_t base = ((size_t)bh * L_ + l) * HD_ + j;
    float q1 = qb[base], q2 = qb[base + 64];
    qb[base]      = q1 * c - q2 * s;
    qb[base + 64] = q1 * s + q2 * c;
    float k1 = kb[base], k2 = kb[base + 64];
    kb[base]      = k1 * c - k2 * s;
    kb[base + 64] = k1 * s + k2 * c;
}

// ---------------------------------------------------------------------------
// Attention + memory path (fp32 SIMT). One block = one (b,h) x 64 query rows.
// ---------------------------------------------------------------------------
__global__ __launch_bounds__(256) void attn_kernel(
    const float* __restrict__ qb, const float* __restrict__ kb,
    const float* __restrict__ vb, const float* __restrict__ gatep,
    const float* __restrict__ memp, const float* __restrict__ normp,
    float* __restrict__ cb)
{
    extern __shared__ char smemraw[];
    float4* Qst4 = (float4*)smemraw;          // 32*65 cells
    float4* Kst4 = Qst4 + 32 * 65;            // 32*65 cells
    float*  Vs   = (float*)(Kst4 + 32 * 65);  // 64*128 floats
    float*  Ps   = Vs + 64 * 128;             // 64*64 floats
    float*  Ms   = (float*)Kst4;              // 128*128, aliases Kst4+Vs
    float*  Ns   = Ps;                        // 128 floats, aliases Ps

    const int tid = threadIdx.x;
    const int tx = tid & 15, ty = tid >> 4;
    const int qt = blockIdx.x;
    const int bh = blockIdx.y;
    const int h  = bh & (H_ - 1);
    const int b  = bh >> 4;

    const float* qblk  = qb + ((size_t)bh * L_ + qt * 64) * HD_;
    const float* kbase = kb + (size_t)bh * L_ * HD_;
    const float* vbase = vb + (size_t)bh * L_ * HD_;

#pragma unroll
    for (int it = 0; it < 8; it++) {
        int item = tid + it * 256;
        int r = item >> 5, d4 = item & 31;
        Qst4[d4 * 65 + r] = *(const float4*)(qblk + r * HD_ + d4 * 4);
    }

    float o[4][8];
#pragma unroll
    for (int i = 0; i < 4; i++)
#pragma unroll
        for (int j = 0; j < 8; j++) o[i][j] = 0.f;
    float mrow[4] = {-1e30f, -1e30f, -1e30f, -1e30f};
    float lrow[4] = {0.f, 0.f, 0.f, 0.f};

    __syncthreads();

    const float scale = 0.08838834764831845f;

    for (int kt = 0; kt < 32; kt++) {
        const float* kblk = kbase + (size_t)kt * 64 * HD_;
        const float* vblk = vbase + (size_t)kt * 64 * HD_;
#pragma unroll
        for (int it = 0; it < 8; it++) {
            int item = tid + it * 256;
            int r = item >> 5, d4 = item & 31;
            Kst4[d4 * 65 + r] = *(const float4*)(kblk + r * HD_ + d4 * 4);
            *(float4*)(Vs + r * HD_ + d4 * 4) = *(const float4*)(vblk + r * HD_ + d4 * 4);
        }
        __syncthreads();

        float s[4][4];
#pragma unroll
        for (int i = 0; i < 4; i++)
#pragma unroll
            for (int j = 0; j < 4; j++) s[i][j] = 0.f;

#pragma unroll 2
        for (int d4 = 0; d4 < 32; d4++) {
            float4 qv[4], kv[4];
#pragma unroll
            for (int i = 0; i < 4; i++) qv[i] = Qst4[d4 * 65 + ty * 4 + i];
#pragma unroll
            for (int j = 0; j < 4; j++) kv[j] = Kst4[d4 * 65 + tx * 4 + j];
#pragma unroll
            for (int i = 0; i < 4; i++)
#pragma unroll
                for (int j = 0; j < 4; j++) {
                    s[i][j] = fmaf(qv[i].x, kv[j].x, s[i][j]);
                    s[i][j] = fmaf(qv[i].y, kv[j].y, s[i][j]);
                    s[i][j] = fmaf(qv[i].z, kv[j].z, s[i][j]);
                    s[i][j] = fmaf(qv[i].w, kv[j].w, s[i][j]);
                }
        }

#pragma unroll
        for (int i = 0; i < 4; i++) {
            float tmax = fmaxf(fmaxf(s[i][0], s[i][1]), fmaxf(s[i][2], s[i][3])) * scale;
#pragma unroll
            for (int off = 8; off >= 1; off >>= 1)
                tmax = fmaxf(tmax, __shfl_xor_sync(0xffffffffu, tmax, off));
            float newm = fmaxf(mrow[i], tmax);
            float corr = expf(mrow[i] - newm);
            mrow[i] = newm;
            float psum = 0.f;
#pragma unroll
            for (int j = 0; j < 4; j++) {
                float pval = expf(s[i][j] * scale - newm);
                s[i][j] = pval;
                psum += pval;
            }
#pragma unroll
            for (int off = 8; off >= 1; off >>= 1)
                psum += __shfl_xor_sync(0xffffffffu, psum, off);
            lrow[i] = lrow[i] * corr + psum;
#pragma unroll
            for (int jj = 0; jj < 8; jj++) o[i][jj] *= corr;
            *(float4*)&Ps[(ty * 4 + i) * 64 + tx * 4] =
                make_float4(s[i][0], s[i][1], s[i][2], s[i][3]);
        }
        __syncthreads();

#pragma unroll 2
        for (int c = 0; c < 64; c++) {
            float4 v0 = *(const float4*)(Vs + c * HD_ + tx * 8);
            float4 v1 = *(const float4*)(Vs + c * HD_ + tx * 8 + 4);
#pragma unroll
            for (int i = 0; i < 4; i++) {
                float pv = Ps[(ty * 4 + i) * 64 + c];
                o[i][0] = fmaf(pv, v0.x, o[i][0]);
                o[i][1] = fmaf(pv, v0.y, o[i][1]);
                o[i][2] = fmaf(pv, v0.z, o[i][2]);
                o[i][3] = fmaf(pv, v0.w, o[i][3]);
                o[i][4] = fmaf(pv, v1.x, o[i][4]);
                o[i][5] = fmaf(pv, v1.y, o[i][5]);
                o[i][6] = fmaf(pv, v1.z, o[i][6]);
                o[i][7] = fmaf(pv, v1.w, o[i][7]);
            }
        }
        __syncthreads();
    }

    // memory path
    const float* mptr = memp + (size_t)bh * HD_ * HD_;
#pragma unroll
    for (int it = 0; it < 16; it++) {
        int item = tid + it * 256;
        *(float4*)(Ms + item * 4) = *(const float4*)(mptr + item * 4);
    }
    if (tid < 32)
        *(float4*)(Ns + tid * 4) = *(const float4*)(normp + (size_t)bh * HD_ + tid * 4);
    __syncthreads();

    float acc2[4][8];
#pragma unroll
    for (int i = 0; i < 4; i++)
#pragma unroll
        for (int j = 0; j < 8; j++) acc2[i][j] = 0.f;
    float den[4] = {0.f, 0.f, 0.f, 0.f};

    const float* Qsf = (const float*)Qst4;
    for (int d4 = 0; d4 < 32; d4++) {
        float qf[4][4];
#pragma unroll
        for (int i = 0; i < 4; i++) {
            const float* qc = Qsf + (size_t)(d4 * 65 + ty * 4 + i) * 4;
#pragma unroll
            for (int u = 0; u < 4; u++) {
                float qv = qc[u];
                qf[i][u] = qv > 0.f ? qv + 1.f : expf(qv);
            }
        }
#pragma unroll
        for (int u = 0; u < 4; u++) {
            int d = d4 * 4 + u;
            float nr = Ns[d];
            float4 m0 = *(const float4*)(Ms + d * HD_ + tx * 8);
            float4 m1 = *(const float4*)(Ms + d * HD_ + tx * 8 + 4);
#pragma unroll
            for (int i = 0; i < 4; i++) {
                float q = qf[i][u];
                den[i]     = fmaf(q, nr,   den[i]);
                acc2[i][0] = fmaf(q, m0.x, acc2[i][0]);
                acc2[i][1] = fmaf(q, m0.y, acc2[i][1]);
                acc2[i][2] = fmaf(q, m0.z, acc2[i][2]);
                acc2[i][3] = fmaf(q, m0.w, acc2[i][3]);
                acc2[i][4] = fmaf(q, m1.x, acc2[i][4]);
                acc2[i][5] = fmaf(q, m1.y, acc2[i][5]);
                acc2[i][6] = fmaf(q, m1.z, acc2[i][6]);
                acc2[i][7] = fmaf(q, m1.w, acc2[i][7]);
            }
        }
    }

    float g  = 1.f / (1.f + expf(-gatep[h]));
    float og = 1.f - g;
#pragma unroll
    for (int i = 0; i < 4; i++) {
        float invl = og / lrow[i];
        float invd = g / den[i];
        int l = qt * 64 + ty * 4 + i;
        float* dst = cb + ((size_t)b * L_ + l) * (H_ * HD_) + h * HD_ + tx * 8;
        float4 r0, r1;
        r0.x = acc2[i][0] * invd + o[i][0] * invl;
        r0.y = acc2[i][1] * invd + o[i][1] * invl;
        r0.z = acc2[i][2] * invd + o[i][2] * invl;
        r0.w = acc2[i][3] * invd + o[i][3] * invl;
        r1.x = acc2[i][4] * invd + o[i][4] * invl;
        r1.y = acc2[i][5] * invd + o[i][5] * invl;
        r1.z = acc2[i][6] * invd + o[i][6] * invl;
        r1.w = acc2[i][7] * invd + o[i][7] * invl;
        *(float4*)dst       = r0;
        *(float4*)(dst + 4) = r1;
    }
}

// ---------------------------------------------------------------------------

extern "C" void kernel_launch(void* const* d_in, const int* in_sizes, int n_in,
                              void* d_out, int out_size)
{
    const float* x      = (const float*)d_in[0];
    const float* Wq     = (const float*)d_in[1];
    const float* Wk     = (const float*)d_in[2];
    const float* Wv     = (const float*)d_in[3];
    const float* Wo     = (const float*)d_in[4];
    const float* gate   = (const float*)d_in[5];
    const float* memory = (const float*)d_in[6];
    const float* norm   = (const float*)d_in[7];
    float* out = (float*)d_out;

    float *qb, *kb, *vb, *cb;
    cudaGetSymbolAddress((void**)&qb, g_q);
    cudaGetSymbolAddress((void**)&kb, g_k);
    cudaGetSymbolAddress((void**)&vb, g_v);
    cudaGetSymbolAddress((void**)&cb, g_c);

    int gsm = 2 * (128 * AS_LD + 32 * BS_LD) * 4;   // 70656 B
    cudaFuncSetAttribute(gemm_tf32<0>, cudaFuncAttributeMaxDynamicSharedMemorySize, gsm);
    cudaFuncSetAttribute(gemm_tf32<1>, cudaFuncAttributeMaxDynamicSharedMemorySize, gsm);

    dim3 gg(16, 32);   // N/128, M/128
    gemm_tf32<0><<<gg, 256, gsm>>>(x, Wq, qb, B_ * L_, H_ * HD_, D_);
    gemm_tf32<0><<<gg, 256, gsm>>>(x, Wk, kb, B_ * L_, H_ * HD_, D_);
    gemm_tf32<0><<<gg, 256, gsm>>>(x, Wv, vb, B_ * L_, H_ * HD_, D_);

    int nrope = B_ * H_ * L_ * 64;
    rope_kernel<<<nrope / 256, 256>>>(qb, kb);

    int smem = (32 * 65 * 2) * 16 + 64 * 128 * 4 + 64 * 64 * 4;  // 115712 B
    cudaFuncSetAttribute(attn_kernel, cudaFuncAttributeMaxDynamicSharedMemorySize, smem);
    attn_kernel<<<dim3(32, 32), 256, smem>>>(qb, kb, vb, gate, memory, norm, cb);

    gemm_tf32<1><<<gg, 256, gsm>>>(cb, Wo, out, B_ * L_, H_ * HD_, D_);
}

// round 4
// speedup vs baseline: 3.6243x; 2.5209x over previous
#include <cuda_runtime.h>
#include <math.h>

#define B_  2
#define L_  2048
#define D_  2048
#define H_  16
#define HD_ 128

// Scratch (static __device__ — no runtime allocation)
__device__ float g_q[(size_t)B_ * H_ * L_ * HD_];
__device__ float g_k[(size_t)B_ * H_ * L_ * HD_];
__device__ float g_v[(size_t)B_ * H_ * L_ * HD_];
__device__ float g_c[(size_t)B_ * L_ * H_ * HD_];

__device__ __forceinline__ unsigned f2tf32(float f) {
    unsigned u;
    asm("cvt.rna.tf32.f32 %0, %1;" : "=r"(u) : "f"(f));
    return u;
}

__device__ __forceinline__ void mma_tf32(float* c, const unsigned* a,
                                         unsigned b0, unsigned b1) {
    asm volatile(
        "mma.sync.aligned.m16n8k8.row.col.f32.tf32.tf32.f32 "
        "{%0,%1,%2,%3},{%4,%5,%6,%7},{%8,%9},{%0,%1,%2,%3};\n"
        : "+f"(c[0]), "+f"(c[1]), "+f"(c[2]), "+f"(c[3])
        : "r"(a[0]), "r"(a[1]), "r"(a[2]), "r"(a[3]), "r"(b0), "r"(b1));
}

// ---------------------------------------------------------------------------
// TF32 tensor-core GEMM (unchanged from round 3 — verified correct).
// ---------------------------------------------------------------------------
#define AS_LD 36
#define BS_LD 132

template <int MODE>
__global__ __launch_bounds__(256, 1) void gemm_tf32(
    const float* __restrict__ A, const float* __restrict__ Bm,
    float* __restrict__ C, int M, int N, int K)
{
    extern __shared__ unsigned sm[];
    unsigned* As = sm;
    unsigned* Bs = sm + 2 * 128 * AS_LD;

    const int tid  = threadIdx.x;
    const int warp = tid >> 5, lane = tid & 31;
    const int qr = lane >> 2, qc = lane & 3;
    const int wm = (warp & 1) * 64;
    const int wn = (warp >> 1) * 32;
    const int bm = blockIdx.y * 128, bn = blockIdx.x * 128;

    const int ar = tid >> 3, ac4 = tid & 7;
    const int br = tid >> 5, bc4 = tid & 31;

    float acc[4][4][4];
#pragma unroll
    for (int mt = 0; mt < 4; mt++)
#pragma unroll
        for (int nt = 0; nt < 4; nt++)
#pragma unroll
            for (int u = 0; u < 4; u++) acc[mt][nt][u] = 0.f;

    float4 ra[4], rb[4];

#pragma unroll
    for (int it = 0; it < 4; it++)
        ra[it] = *(const float4*)(A + (size_t)(bm + ar + it * 32) * K + ac4 * 4);
#pragma unroll
    for (int it = 0; it < 4; it++)
        rb[it] = *(const float4*)(Bm + (size_t)(br + it * 8) * N + bn + bc4 * 4);

    int p = 0;
#pragma unroll
    for (int it = 0; it < 4; it++) {
        unsigned* d = As + (ar + it * 32) * AS_LD + ac4 * 4;
        d[0] = f2tf32(ra[it].x); d[1] = f2tf32(ra[it].y);
        d[2] = f2tf32(ra[it].z); d[3] = f2tf32(ra[it].w);
    }
#pragma unroll
    for (int it = 0; it < 4; it++) {
        unsigned* d = Bs + (br + it * 8) * BS_LD + bc4 * 4;
        d[0] = f2tf32(rb[it].x); d[1] = f2tf32(rb[it].y);
        d[2] = f2tf32(rb[it].z); d[3] = f2tf32(rb[it].w);
    }
    __syncthreads();

    const int NCHUNK = K >> 5;
    for (int ch = 0; ch < NCHUNK; ch++) {
        if (ch + 1 < NCHUNK) {
            int k0 = (ch + 1) << 5;
#pragma unroll
            for (int it = 0; it < 4; it++)
                ra[it] = *(const float4*)(A + (size_t)(bm + ar + it * 32) * K + k0 + ac4 * 4);
#pragma unroll
            for (int it = 0; it < 4; it++)
                rb[it] = *(const float4*)(Bm + (size_t)(k0 + br + it * 8) * N + bn + bc4 * 4);
        }

        const unsigned* Ab = As + p * 128 * AS_LD;
        const unsigned* Bb = Bs + p * 32 * BS_LD;

#pragma unroll
        for (int s = 0; s < 4; s++) {
            const int kb = s * 8;
            unsigned a[4][4], b[4][2];
#pragma unroll
            for (int mt = 0; mt < 4; mt++) {
                int m = wm + mt * 16 + qr;
                a[mt][0] = Ab[m * AS_LD + kb + qc];
                a[mt][1] = Ab[(m + 8) * AS_LD + kb + qc];
                a[mt][2] = Ab[m * AS_LD + kb + qc + 4];
                a[mt][3] = Ab[(m + 8) * AS_LD + kb + qc + 4];
            }
#pragma unroll
            for (int nt = 0; nt < 4; nt++) {
                int n = wn + nt * 8 + qr;
                b[nt][0] = Bb[(kb + qc) * BS_LD + n];
                b[nt][1] = Bb[(kb + qc + 4) * BS_LD + n];
            }
#pragma unroll
            for (int mt = 0; mt < 4; mt++)
#pragma unroll
                for (int nt = 0; nt < 4; nt++)
                    mma_tf32(acc[mt][nt], a[mt], b[nt][0], b[nt][1]);
        }

        if (ch + 1 < NCHUNK) {
            int q = p ^ 1;
            unsigned* Aw = As + q * 128 * AS_LD;
            unsigned* Bw = Bs + q * 32 * BS_LD;
#pragma unroll
            for (int it = 0; it < 4; it++) {
                unsigned* d = Aw + (ar + it * 32) * AS_LD + ac4 * 4;
                d[0] = f2tf32(ra[it].x); d[1] = f2tf32(ra[it].y);
                d[2] = f2tf32(ra[it].z); d[3] = f2tf32(ra[it].w);
            }
#pragma unroll
            for (int it = 0; it < 4; it++) {
                unsigned* d = Bw + (br + it * 8) * BS_LD + bc4 * 4;
                d[0] = f2tf32(rb[it].x); d[1] = f2tf32(rb[it].y);
                d[2] = f2tf32(rb[it].z); d[3] = f2tf32(rb[it].w);
            }
            __syncthreads();
            p = q;
        }
    }

#pragma unroll
    for (int mt = 0; mt < 4; mt++) {
#pragma unroll
        for (int nt = 0; nt < 4; nt++) {
            int row = bm + wm + mt * 16 + qr;
            int col = bn + wn + nt * 8 + 2 * qc;
            float2 r0 = make_float2(acc[mt][nt][0], acc[mt][nt][1]);
            float2 r1 = make_float2(acc[mt][nt][2], acc[mt][nt][3]);
            if (MODE == 0) {
                int b0 = row >> 11, l0 = row & (L_ - 1);
                int h = col >> 7, d = col & (HD_ - 1);
                *(float2*)(C + ((((size_t)b0 * H_ + h) * L_ + l0) * HD_ + d)) = r0;
                int row1 = row + 8;
                int b1 = row1 >> 11, l1 = row1 & (L_ - 1);
                *(float2*)(C + ((((size_t)b1 * H_ + h) * L_ + l1) * HD_ + d)) = r1;
            } else {
                *(float2*)(C + (size_t)row * N + col) = r0;
                *(float2*)(C + (size_t)(row + 8) * N + col) = r1;
            }
        }
    }
}

// ---------------------------------------------------------------------------
// RoPE in-place on q and k.
// ---------------------------------------------------------------------------
__global__ void rope_kernel(float* __restrict__ qb, float* __restrict__ kb)
{
    int idx = blockIdx.x * blockDim.x + threadIdx.x;
    if (idx >= B_ * H_ * L_ * 64) return;
    int j  = idx & 63;
    int l  = (idx >> 6) & (L_ - 1);
    int bh = idx >> 17;

    float freq = expf(-9.210340371976184f * (float)j * (1.0f / 64.0f));
    float ang = (float)l * freq;
    float s, c;
    sincosf(ang, &s, &c);

    size_t base = ((size_t)bh * L_ + l) * HD_ + j;
    float q1 = qb[base], q2 = qb[base + 64];
    qb[base]      = q1 * c - q2 * s;
    qb[base + 64] = q1 * s + q2 * c;
    float k1 = kb[base], k2 = kb[base + 64];
    kb[base]      = k1 * c - k2 * s;
    kb[base + 64] = k1 * s + k2 * c;
}

// ---------------------------------------------------------------------------
// Tensor-core attention + memory path.
// Block = 128 Q-rows x one (b,h). 8 warps, each owns 16 full rows.
// S and PV and the q_f@memory GEMM all via m16n8k8 tf32 MMA.
// smem word layout:
//   Qs [128][132] @ 0       (q tile, tf32; transformed in-place to q_f)
//   Ks [64][132]  @ 16896
//   Vs [64][136]  @ 25344
//   Ps [128][68]  @ 34048   (softmax P tile, tf32)
//   Ms [128][136] @ 16896   (memory, aliases Ks..part of Ps, epilogue only)
//   Ns [128]      @ 34304   (norm_term fp32, aliases Ps, epilogue only)
// ---------------------------------------------------------------------------
#define QS_OFF 0
#define KS_OFF 16896
#define VS_OFF 25344
#define PS_OFF 34048
#define MS_OFF 16896
#define NS_OFF 34304
#define LDQ 132
#define LDK 132
#define LDV 136
#define LDP 68
#define LDM 136
#define ATTN_SMEM (42752 * 4)

__global__ __launch_bounds__(256, 1) void attn_tc(
    const float* __restrict__ qb, const float* __restrict__ kb,
    const float* __restrict__ vb, const float* __restrict__ gatep,
    const float* __restrict__ memp, const float* __restrict__ normp,
    float* __restrict__ cb)
{
    extern __shared__ float smf[];
    unsigned* smu = (unsigned*)smf;

    const int tid = threadIdx.x;
    const int w = tid >> 5, lane = tid & 31;
    const int qr = lane >> 2, qc = lane & 3;
    const int qt = blockIdx.x;          // 0..15 (128 rows each)
    const int bh = blockIdx.y;          // 0..31
    const int h  = bh & (H_ - 1);
    const int b  = bh >> 4;
    const int m0 = w * 16 + qr;         // this thread's row (and m0+8)

    const float* qblk  = qb + ((size_t)bh * L_ + qt * 128) * HD_;
    const float* kbase = kb + (size_t)bh * L_ * HD_;
    const float* vbase = vb + (size_t)bh * L_ * HD_;

    // ---- load Q tile (tf32) ----
#pragma unroll
    for (int it = 0; it < 16; it++) {
        int row = w + 8 * it;
        float4 v = *(const float4*)(qblk + (size_t)row * HD_ + lane * 4);
        *(uint4*)&smu[QS_OFF + row * LDQ + lane * 4] =
            make_uint4(f2tf32(v.x), f2tf32(v.y), f2tf32(v.z), f2tf32(v.w));
    }

    float o[16][4];
#pragma unroll
    for (int nt = 0; nt < 16; nt++)
#pragma unroll
        for (int u = 0; u < 4; u++) o[nt][u] = 0.f;
    float mrow0 = -1e30f, mrow1 = -1e30f;
    float lrow0 = 0.f, lrow1 = 0.f;

    const float scale = 0.08838834764831845f;   // 128^-0.5

    for (int kt = 0; kt < 32; kt++) {
        // ---- load K,V tiles (tf32) ----
        const float* kblk = kbase + (size_t)kt * 64 * HD_;
        const float* vblk = vbase + (size_t)kt * 64 * HD_;
#pragma unroll
        for (int it = 0; it < 8; it++) {
            int row = w + 8 * it;
            float4 kv = *(const float4*)(kblk + (size_t)row * HD_ + lane * 4);
            *(uint4*)&smu[KS_OFF + row * LDK + lane * 4] =
                make_uint4(f2tf32(kv.x), f2tf32(kv.y), f2tf32(kv.z), f2tf32(kv.w));
            float4 vv = *(const float4*)(vblk + (size_t)row * HD_ + lane * 4);
            *(uint4*)&smu[VS_OFF + row * LDV + lane * 4] =
                make_uint4(f2tf32(vv.x), f2tf32(vv.y), f2tf32(vv.z), f2tf32(vv.w));
        }
        __syncthreads();

        // ---- S = Q K^T : warp tile 16x64, 8 n-tiles, 16 k-steps ----
        float sa[8][4];
#pragma unroll
        for (int nt = 0; nt < 8; nt++)
#pragma unroll
            for (int u = 0; u < 4; u++) sa[nt][u] = 0.f;

#pragma unroll
        for (int ks = 0; ks < 16; ks++) {
            const int kb8 = ks * 8;
            unsigned a[4];
            a[0] = smu[QS_OFF + m0 * LDQ + kb8 + qc];
            a[1] = smu[QS_OFF + (m0 + 8) * LDQ + kb8 + qc];
            a[2] = smu[QS_OFF + m0 * LDQ + kb8 + qc + 4];
            a[3] = smu[QS_OFF + (m0 + 8) * LDQ + kb8 + qc + 4];
#pragma unroll
            for (int nt = 0; nt < 8; nt++) {
                int n = nt * 8 + qr;
                unsigned b0 = smu[KS_OFF + n * LDK + kb8 + qc];
                unsigned b1 = smu[KS_OFF + n * LDK + kb8 + qc + 4];
                mma_tf32(sa[nt], a, b0, b1);
            }
        }

        // ---- online softmax (rows m0 and m0+8, warp-local) ----
        float cand0 = -1e30f, cand1 = -1e30f;
#pragma unroll
        for (int nt = 0; nt < 8; nt++) {
            cand0 = fmaxf(cand0, fmaxf(sa[nt][0], sa[nt][1]));
            cand1 = fmaxf(cand1, fmaxf(sa[nt][2], sa[nt][3]));
        }
        cand0 *= scale; cand1 *= scale;
        cand0 = fmaxf(cand0, __shfl_xor_sync(0xffffffffu, cand0, 1));
        cand0 = fmaxf(cand0, __shfl_xor_sync(0xffffffffu, cand0, 2));
        cand1 = fmaxf(cand1, __shfl_xor_sync(0xffffffffu, cand1, 1));
        cand1 = fmaxf(cand1, __shfl_xor_sync(0xffffffffu, cand1, 2));

        float newm0 = fmaxf(mrow0, cand0), newm1 = fmaxf(mrow1, cand1);
        float corr0 = __expf(mrow0 - newm0), corr1 = __expf(mrow1 - newm1);
        mrow0 = newm0; mrow1 = newm1;

        float psum0 = 0.f, psum1 = 0.f;
#pragma unroll
        for (int nt = 0; nt < 8; nt++) {
            float p0 = __expf(sa[nt][0] * scale - newm0);
            float p1 = __expf(sa[nt][1] * scale - newm0);
            float p2 = __expf(sa[nt][2] * scale - newm1);
            float p3 = __expf(sa[nt][3] * scale - newm1);
            psum0 += p0 + p1; psum1 += p2 + p3;
            float2 lo, hi;
            lo.x = __uint_as_float(f2tf32(p0)); lo.y = __uint_as_float(f2tf32(p1));
            hi.x = __uint_as_float(f2tf32(p2)); hi.y = __uint_as_float(f2tf32(p3));
            *(float2*)&smf[PS_OFF + m0 * LDP + nt * 8 + 2 * qc] = lo;
            *(float2*)&smf[PS_OFF + (m0 + 8) * LDP + nt * 8 + 2 * qc] = hi;
        }
        psum0 += __shfl_xor_sync(0xffffffffu, psum0, 1);
        psum0 += __shfl_xor_sync(0xffffffffu, psum0, 2);
        psum1 += __shfl_xor_sync(0xffffffffu, psum1, 1);
        psum1 += __shfl_xor_sync(0xffffffffu, psum1, 2);
        lrow0 = lrow0 * corr0 + psum0;
        lrow1 = lrow1 * corr1 + psum1;

#pragma unroll
        for (int nt = 0; nt < 16; nt++) {
            o[nt][0] *= corr0; o[nt][1] *= corr0;
            o[nt][2] *= corr1; o[nt][3] *= corr1;
        }
        __syncthreads();   // P visible to all warps

        // ---- O += P V : 16 n-tiles (d), 8 k-steps (keys) ----
#pragma unroll
        for (int ks = 0; ks < 8; ks++) {
            const int kb8 = ks * 8;
            unsigned a[4];
            a[0] = __float_as_uint(smf[PS_OFF + m0 * LDP + kb8 + qc]);
            a[1] = __float_as_uint(smf[PS_OFF + (m0 + 8) * LDP + kb8 + qc]);
            a[2] = __float_as_uint(smf[PS_OFF + m0 * LDP + kb8 + qc + 4]);
            a[3] = __float_as_uint(smf[PS_OFF + (m0 + 8) * LDP + kb8 + qc + 4]);
#pragma unroll
            for (int nt = 0; nt < 16; nt++) {
                int n = nt * 8 + qr;
                unsigned b0 = smu[VS_OFF + (kb8 + qc) * LDV + n];
                unsigned b1 = smu[VS_OFF + (kb8 + qc + 4) * LDV + n];
                mma_tf32(o[nt], a, b0, b1);
            }
        }
        __syncthreads();   // protect Ks/Vs before next tile's stores
    }

    // ================== epilogue: memory path ==================
    // load memory (tf32) into Ms, norm (fp32) into Ns, q_f in place over Qs
    const float* mptr = memp + (size_t)bh * HD_ * HD_;
#pragma unroll
    for (int it = 0; it < 16; it++) {
        int row = w + 8 * it;
        float4 v = *(const float4*)(mptr + (size_t)row * HD_ + lane * 4);
        *(uint4*)&smu[MS_OFF + row * LDM + lane * 4] =
            make_uint4(f2tf32(v.x), f2tf32(v.y), f2tf32(v.z), f2tf32(v.w));
    }
    if (tid < 128) smf[NS_OFF + tid] = normp[(size_t)bh * HD_ + tid];

    // q_f = elu(q)+1 in place (each thread touches only its own elements)
#pragma unroll
    for (int it = 0; it < 64; it++) {
        int e = tid + it * 256;           // 0..16383
        int row = e >> 7, col = e & 127;
        float qv = smf[QS_OFF + row * LDQ + col];
        float qf = qv > 0.f ? qv + 1.f : __expf(qv);
        smu[QS_OFF + row * LDQ + col] = f2tf32(qf);
    }
    __syncthreads();

    // denom (fp32 SIMT): rows m0, m0+8
    float den0 = 0.f, den1 = 0.f;
#pragma unroll 8
    for (int j = 0; j < 32; j++) {
        int d = qc + 4 * j;
        float nv = smf[NS_OFF + d];
        den0 = fmaf(smf[QS_OFF + m0 * LDQ + d], nv, den0);
        den1 = fmaf(smf[QS_OFF + (m0 + 8) * LDQ + d], nv, den1);
    }
    den0 += __shfl_xor_sync(0xffffffffu, den0, 1);
    den0 += __shfl_xor_sync(0xffffffffu, den0, 2);
    den1 += __shfl_xor_sync(0xffffffffu, den1, 1);
    den1 += __shfl_xor_sync(0xffffffffu, den1, 2);

    const float g  = 1.f / (1.f + __expf(-gatep[h]));
    const float og = 1.f - g;
    const float invl0 = og / lrow0, invl1 = og / lrow1;
    const float invd0 = g / den0,   invd1 = g / den1;

    const int l0 = qt * 128 + m0;
    float* dst0 = cb + ((size_t)b * L_ + l0) * (H_ * HD_) + h * HD_;
    float* dst1 = cb + ((size_t)b * L_ + l0 + 8) * (H_ * HD_) + h * HD_;

    // mem_out MMA in two passes of 8 n-tiles, combining + store per pass
#pragma unroll
    for (int pass = 0; pass < 2; pass++) {
        float ma[8][4];
#pragma unroll
        for (int nt = 0; nt < 8; nt++)
#pragma unroll
            for (int u = 0; u < 4; u++) ma[nt][u] = 0.f;

#pragma unroll
        for (int ks = 0; ks < 16; ks++) {
            const int kb8 = ks * 8;
            unsigned a[4];
            a[0] = smu[QS_OFF + m0 * LDQ + kb8 + qc];
            a[1] = smu[QS_OFF + (m0 + 8) * LDQ + kb8 + qc];
            a[2] = smu[QS_OFF + m0 * LDQ + kb8 + qc + 4];
            a[3] = smu[QS_OFF + (m0 + 8) * LDQ + kb8 + qc + 4];
#pragma unroll
            for (int nt = 0; nt < 8; nt++) {
                int n = (pass * 8 + nt) * 8 + qr;
                unsigned b0 = smu[MS_OFF + (kb8 + qc) * LDM + n];
                unsigned b1 = smu[MS_OFF + (kb8 + qc + 4) * LDM + n];
                mma_tf32(ma[nt], a, b0, b1);
            }
        }

#pragma unroll
        for (int nt = 0; nt < 8; nt++) {
            int gnt = pass * 8 + nt;
            int col = gnt * 8 + 2 * qc;
            float2 r0, r1;
            r0.x = ma[nt][0] * invd0 + o[gnt][0] * invl0;
            r0.y = ma[nt][1] * invd0 + o[gnt][1] * invl0;
            r1.x = ma[nt][2] * invd1 + o[gnt][2] * invl1;
            r1.y = ma[nt][3] * invd1 + o[gnt][3] * invl1;
            *(float2*)(dst0 + col) = r0;
            *(float2*)(dst1 + col) = r1;
        }
    }
}

// ---------------------------------------------------------------------------

extern "C" void kernel_launch(void* const* d_in, const int* in_sizes, int n_in,
                              void* d_out, int out_size)
{
    const float* x      = (const float*)d_in[0];
    const float* Wq     = (const float*)d_in[1];
    const float* Wk     = (const float*)d_in[2];
    const float* Wv     = (const float*)d_in[3];
    const float* Wo     = (const float*)d_in[4];
    const float* gate   = (const float*)d_in[5];
    const float* memory = (const float*)d_in[6];
    const float* norm   = (const float*)d_in[7];
    float* out = (float*)d_out;

    float *qb, *kb, *vb, *cb;
    cudaGetSymbolAddress((void**)&qb, g_q);
    cudaGetSymbolAddress((void**)&kb, g_k);
    cudaGetSymbolAddress((void**)&vb, g_v);
    cudaGetSymbolAddress((void**)&cb, g_c);

    int gsm = 2 * (128 * AS_LD + 32 * BS_LD) * 4;   // 70656 B
    cudaFuncSetAttribute(gemm_tf32<0>, cudaFuncAttributeMaxDynamicSharedMemorySize, gsm);
    cudaFuncSetAttribute(gemm_tf32<1>, cudaFuncAttributeMaxDynamicSharedMemorySize, gsm);

    dim3 gg(16, 32);   // N/128, M/128
    gemm_tf32<0><<<gg, 256, gsm>>>(x, Wq, qb, B_ * L_, H_ * HD_, D_);
    gemm_tf32<0><<<gg, 256, gsm>>>(x, Wk, kb, B_ * L_, H_ * HD_, D_);
    gemm_tf32<0><<<gg, 256, gsm>>>(x, Wv, vb, B_ * L_, H_ * HD_, D_);

    int nrope = B_ * H_ * L_ * 64;
    rope_kernel<<<nrope / 256, 256>>>(qb, kb);

    cudaFuncSetAttribute(attn_tc, cudaFuncAttributeMaxDynamicSharedMemorySize, ATTN_SMEM);
    attn_tc<<<dim3(16, 32), 256, ATTN_SMEM>>>(qb, kb, vb, gate, memory, norm, cb);

    gemm_tf32<1><<<gg, 256, gsm>>>(cb, Wo, out, B_ * L_, H_ * HD_, D_);
}